// round 16
// baseline (speedup 1.0000x reference)
#include <cuda_runtime.h>
#include <cuda_bf16.h>
#include <math.h>
#include <stdint.h>

// ---------------- problem constants ----------------
constexpr int NB   = 4;
constexpr int SEQ  = 1024;
constexpr int DIN  = 1024;
constexpr int NH   = 16;
constexpr int MTOT = NB * SEQ;                       // 4096
constexpr size_t OUT1_ELEMS = (size_t)MTOT * DIN;    // 4,194,304
// d_out layout: [ out (4M floats) | attention (64M floats) ]

// ---------------- scratch (device globals; no allocation) ----------------
__device__ float g_O1 [OUT1_ELEMS];                  // final proj + bias + resid
// bf16-split planes for GEMM inputs (X reused across GEMMs)
__device__ __nv_bfloat16 g_Xh[OUT1_ELEMS];           // X hi plane [m][k]
__device__ __nv_bfloat16 g_Xl[OUT1_ELEMS];           // X lo plane [m][k]
__device__ __nv_bfloat16 g_Wh[(size_t)DIN * DIN];    // W hi plane TRANSPOSED [n][k]
__device__ __nv_bfloat16 g_Wl[(size_t)DIN * DIN];    // W lo plane TRANSPOSED [n][k]
// projected Q/K/V in bf16-split head layout [(b*NH+h)*SEQ + s][64]
__device__ __nv_bfloat16 g_sH[3][OUT1_ELEMS];
__device__ __nv_bfloat16 g_sL[3][OUT1_ELEMS];

// =====================================================================
// helpers (plain-sm_103-safe: ldmatrix + mma.sync + cp.async only)
// =====================================================================
__device__ __forceinline__ uint32_t smem_u32(const void* p) {
    return (uint32_t)__cvta_generic_to_shared(p);
}

#define LDSM_X4(r, addr)                                                        \
    asm volatile("ldmatrix.sync.aligned.m8n8.x4.shared.b16 {%0,%1,%2,%3}, [%4];"\
        : "=r"((r)[0]), "=r"((r)[1]), "=r"((r)[2]), "=r"((r)[3]) : "r"(addr))

#define LDSM_X4_T(r, addr)                                                      \
    asm volatile("ldmatrix.sync.aligned.m8n8.x4.trans.shared.b16 {%0,%1,%2,%3}, [%4];"\
        : "=r"((r)[0]), "=r"((r)[1]), "=r"((r)[2]), "=r"((r)[3]) : "r"(addr))

#define MMA_BF16(d, a, b0, b1)                                                  \
    asm volatile("mma.sync.aligned.m16n8k16.row.col.f32.bf16.bf16.f32 "         \
        "{%0,%1,%2,%3}, {%4,%5,%6,%7}, {%8,%9}, {%0,%1,%2,%3};"                 \
        : "+f"((d)[0]), "+f"((d)[1]), "+f"((d)[2]), "+f"((d)[3])                \
        : "r"((a)[0]), "r"((a)[1]), "r"((a)[2]), "r"((a)[3]), "r"(b0), "r"(b1))

__device__ __forceinline__ void cp16(uint32_t dst, const void* src) {
    asm volatile("cp.async.cg.shared.global [%0], [%1], 16;" :: "r"(dst), "l"(src));
}
#define CP_COMMIT() asm volatile("cp.async.commit_group;" ::: "memory")
#define CP_WAIT(n)  asm volatile("cp.async.wait_group %0;" :: "n"(n) : "memory")

// pack two floats to bf16x2 (RN): e0 -> low 16 bits, e1 -> high 16 bits
__device__ __forceinline__ uint32_t pack2(float e0, float e1) {
    uint32_t r;
    asm("cvt.rn.bf16x2.f32 %0, %1, %2;" : "=r"(r) : "f"(e1), "f"(e0));
    return r;
}
__device__ __forceinline__ float lo_half_f(uint32_t p)  { return __uint_as_float(p << 16); }
__device__ __forceinline__ float hi_half_f(uint32_t p)  { return __uint_as_float(p & 0xFFFF0000u); }

// =====================================================================
// cvt_x: elementwise fp32 -> (hi, lo) bf16 planes, same [m][k] layout.
// =====================================================================
__global__ __launch_bounds__(256) void cvt_x(const float* __restrict__ X)
{
    size_t i = ((size_t)blockIdx.x * 256 + threadIdx.x) * 4;
    float4 v = *(const float4*)(X + i);
    uint32_t hp0 = pack2(v.x, v.y);
    uint32_t hp1 = pack2(v.z, v.w);
    float lx = v.x - lo_half_f(hp0), ly = v.y - hi_half_f(hp0);
    float lz = v.z - lo_half_f(hp1), lw = v.w - hi_half_f(hp1);
    *(uint2*)(g_Xh + i) = make_uint2(hp0, hp1);
    *(uint2*)(g_Xl + i) = make_uint2(pack2(lx, ly), pack2(lz, lw));
}

// =====================================================================
// cvt_w: W[k][n] fp32 -> transposed bf16 planes g_W{h,l}[n][k].
// =====================================================================
__global__ __launch_bounds__(256) void cvt_w(const float* __restrict__ W)
{
    __shared__ float t[32][33];
    const int k0 = blockIdx.y * 32, n0 = blockIdx.x * 32;
    const int tx = threadIdx.x & 31, ty = threadIdx.x >> 5;
    #pragma unroll
    for (int p = 0; p < 4; ++p) {
        int r = ty + p * 8;
        t[r][tx] = W[(size_t)(k0 + r) * DIN + n0 + tx];
    }
    __syncthreads();
    const int nl = threadIdx.x >> 4;
    const int pr = threadIdx.x & 15;
    #pragma unroll
    for (int p = 0; p < 2; ++p) {
        int n = nl + p * 16;
        float a = t[2 * pr][n], b = t[2 * pr + 1][n];
        uint32_t hp = pack2(a, b);
        float la = a - lo_half_f(hp), lb = b - hi_half_f(hp);
        size_t off = (size_t)(n0 + n) * DIN + k0 + 2 * pr;
        *(uint32_t*)(g_Wh + off) = hp;
        *(uint32_t*)(g_Wl + off) = pack2(la, lb);
    }
}

// =====================================================================
// HMMA GEMM (R12-validated math) + cp.async double-buffered mainloop.
// C = X W via 3 bf16 products (AhBh + AhBl + AlBh).
// CTA tile 128x128, K-chunk 32, 256 threads = 8 warps (4M x 2N).
// which 0/1/2: epilogue -> bf16 hi/lo head-layout planes g_sH/g_sL[which].
// which 3    : epilogue -> g_O1 fp32 (+bias +resid).
// =====================================================================
constexpr int SPITCH = 80;
constexpr int PLANE  = 128 * SPITCH;       // 10240 B
constexpr int BUFSZ  = 4 * PLANE;          // 40960 B per stage buffer
constexpr int GEMM_SMEM = 2 * BUFSZ;       // 81920 B dynamic

__device__ __forceinline__ void stage_chunk(
    uint32_t sbase, const __nv_bfloat16* const* srcs, int k0, int tid)
{
    #pragma unroll
    for (int pl = 0; pl < 4; ++pl) {
        const __nv_bfloat16* s = srcs[pl] + k0;
        #pragma unroll
        for (int it = 0; it < 2; ++it) {
            int idx = tid + it * 256;          // 0..511 16B-units
            int r = idx >> 2, u = idx & 3;
            cp16(sbase + pl * PLANE + r * SPITCH + u * 16,
                 s + (size_t)r * DIN + u * 8);
        }
    }
}

__global__ __launch_bounds__(256) void gemm_mma(
    const float* __restrict__ bias, const float* __restrict__ resid, int which)
{
    extern __shared__ __align__(16) unsigned char smem[];
    const uint32_t sb = smem_u32(smem);

    const int tid = threadIdx.x;
    const int w   = tid >> 5, ln = tid & 31;
    const int wm  = w & 3, wn = w >> 2;
    const int m0  = blockIdx.y * 128;
    const int n0  = blockIdx.x * 128;

    const __nv_bfloat16* srcs[4] = {
        g_Xh + (size_t)m0 * DIN, g_Xl + (size_t)m0 * DIN,
        g_Wh + (size_t)n0 * DIN, g_Wl + (size_t)n0 * DIN };

    const int a_r = (ln & 7) + ((ln >> 3) & 1) * 8;
    const int a_k = ((ln >> 4) & 1) * 8;
    const int b_n = (ln & 7) + ((ln >> 4) & 1) * 8;
    const int b_k = ((ln >> 3) & 1) * 8;

    float acc[2][8][4];
    #pragma unroll
    for (int i = 0; i < 2; ++i)
        #pragma unroll
        for (int j = 0; j < 8; ++j)
            #pragma unroll
            for (int e = 0; e < 4; ++e) acc[i][j][e] = 0.f;

    // prologue: stage chunks 0 and 1
    stage_chunk(sb,         srcs, 0,  tid); CP_COMMIT();
    stage_chunk(sb + BUFSZ, srcs, 32, tid); CP_COMMIT();

    for (int ch = 0; ch < 32; ++ch) {
        if (ch < 31) { CP_WAIT(1); } else { CP_WAIT(0); }
        __syncthreads();
        const uint32_t bb = sb + (ch & 1) * BUFSZ;

        #pragma unroll
        for (int kk = 0; kk < 32; kk += 16) {
            uint32_t ah[2][4], al[2][4];
            #pragma unroll
            for (int mf = 0; mf < 2; ++mf) {
                uint32_t aaddr = bb + (wm * 32 + mf * 16 + a_r) * SPITCH + (kk + a_k) * 2;
                LDSM_X4(ah[mf], aaddr);
                LDSM_X4(al[mf], aaddr + PLANE);
            }
            #pragma unroll
            for (int t = 0; t < 4; ++t) {
                uint32_t bh[4], bl[4];
                uint32_t baddr = bb + 2 * PLANE +
                                 (wn * 64 + t * 16 + b_n) * SPITCH + (kk + b_k) * 2;
                LDSM_X4(bh, baddr);
                LDSM_X4(bl, baddr + PLANE);
                #pragma unroll
                for (int mf = 0; mf < 2; ++mf)
                    #pragma unroll
                    for (int hv = 0; hv < 2; ++hv) {
                        float* d = acc[mf][t * 2 + hv];
                        MMA_BF16(d, ah[mf], bh[2 * hv], bh[2 * hv + 1]);
                        MMA_BF16(d, ah[mf], bl[2 * hv], bl[2 * hv + 1]);
                        MMA_BF16(d, al[mf], bh[2 * hv], bh[2 * hv + 1]);
                    }
            }
        }
        __syncthreads();   // all warps done reading buf (ch&1) before restaging it
        if (ch + 2 < 32) {
            stage_chunk(bb, srcs, (ch + 2) * 32, tid);
            CP_COMMIT();
        }
    }

    const int rbase = m0 + wm * 32 + (ln >> 2);
    const int cbase = n0 + wn * 64 + (ln & 3) * 2;
    if (which < 3) {
        // bf16-split head-layout epilogue: row m -> (b, s); col c -> (h, d)
        __nv_bfloat16* oh = g_sH[which];
        __nv_bfloat16* ol = g_sL[which];
        #pragma unroll
        for (int mf = 0; mf < 2; ++mf)
            #pragma unroll
            for (int nf = 0; nf < 8; ++nf) {
                int c = cbase + nf * 8;
                int h = c >> 6, d = c & 63;
                float bx = bias[c], by = bias[c + 1];
                #pragma unroll
                for (int half = 0; half < 2; ++half) {
                    int m = rbase + mf * 16 + half * 8;
                    int b = m >> 10, s = m & 1023;
                    float ox = acc[mf][nf][2 * half + 0] + bx;
                    float oy = acc[mf][nf][2 * half + 1] + by;
                    uint32_t hp = pack2(ox, oy);
                    uint32_t lp = pack2(ox - lo_half_f(hp), oy - hi_half_f(hp));
                    size_t off = ((size_t)((b * NH + h) * SEQ + s)) * 64 + d;
                    *(uint32_t*)(oh + off) = hp;
                    *(uint32_t*)(ol + off) = lp;
                }
            }
    } else {
        #pragma unroll
        for (int mf = 0; mf < 2; ++mf)
            #pragma unroll
            for (int nf = 0; nf < 8; ++nf) {
                int c = cbase + nf * 8;
                float bx = bias[c], by = bias[c + 1];
                #pragma unroll
                for (int half = 0; half < 2; ++half) {
                    int r = rbase + mf * 16 + half * 8;
                    float2 rv = *(const float2*)(resid + (size_t)r * DIN + c);
                    float ox = acc[mf][nf][2 * half + 0] + bx + rv.x;
                    float oy = acc[mf][nf][2 * half + 1] + by + rv.y;
                    *(float2*)(g_O1 + (size_t)r * DIN + c) = make_float2(ox, oy);
                }
            }
    }
}

// =====================================================================
// Tensor-core flash attention (R13-validated, unchanged).
// =====================================================================
constexpr int APB = 144;
constexpr int APLANE = 64 * APB;              // 9216
constexpr int OFF_QH = 0;
constexpr int OFF_QL = OFF_QH + APLANE;
constexpr int OFF_KH = OFF_QL + APLANE;       // reused for Vh
constexpr int OFF_KL = OFF_KH + APLANE;       // reused for Vl
constexpr int OFF_PM = OFF_KL + APLANE;
constexpr int OFF_PS = OFF_PM + 512;
constexpr int OFF_RM = OFF_PS + 512;
constexpr int OFF_RL = OFF_RM + 256;
constexpr int OFF_QM = OFF_RL + 256;
constexpr int OFF_KM = OFF_QM + 256;
constexpr int ATT_SM = OFF_KM + 256;          // 38912 B (static)

__global__ __launch_bounds__(256) void attn_mma(
    const float* __restrict__ qmask, const float* __restrict__ kmask,
    float* __restrict__ att)
{
    __shared__ __align__(16) unsigned char SM[ATT_SM];
    const uint32_t sb = smem_u32(SM);
    float* pm   = (float*)(SM + OFF_PM);
    float* ps   = (float*)(SM + OFF_PS);
    float* rowM = (float*)(SM + OFF_RM);
    float* rowL = (float*)(SM + OFF_RL);
    float* qmr  = (float*)(SM + OFF_QM);
    float* skm  = (float*)(SM + OFF_KM);

    const int tid = threadIdx.x;
    const int w   = tid >> 5, ln = tid & 31;
    const int wm  = w & 3, wn = w >> 2;
    const int g   = ln >> 2, t = ln & 3;
    const int bh  = blockIdx.y;
    const int b   = bh >> 4, h = bh & 15;
    const int q0  = blockIdx.x << 6;

    const int a_r = (ln & 7) + ((ln >> 3) & 1) * 8;
    const int a_k = ((ln >> 4) & 1) * 8;
    const int b_n = (ln & 7) + ((ln >> 4) & 1) * 8;
    const int b_k = ((ln >> 3) & 1) * 8;
    const int v_r = (ln & 7) + ((ln >> 3) & 1) * 8;
    const int v_c = ((ln >> 4) & 1) * 8;

    {
        const __nv_bfloat16* qh = g_sH[0] + ((size_t)bh * SEQ + q0) * 64;
        const __nv_bfloat16* ql = g_sL[0] + ((size_t)bh * SEQ + q0) * 64;
        #pragma unroll
        for (int it = 0; it < 2; ++it) {
            int idx = tid + it * 256;
            int r = idx >> 3, u = idx & 7;
            *(uint4*)(SM + OFF_QH + r * APB + u * 16) = *(const uint4*)(qh + r * 64 + u * 8);
            *(uint4*)(SM + OFF_QL + r * APB + u * 16) = *(const uint4*)(ql + r * 64 + u * 8);
        }
    }
    if (tid < 64) {
        qmr[tid]  = qmask[b * SEQ + q0 + tid];
        rowM[tid] = -INFINITY;
        rowL[tid] = 0.f;
    }

    float cacc[8][4];
    #pragma unroll
    for (int i = 0; i < 8; ++i)
        #pragma unroll
        for (int e = 0; e < 4; ++e) cacc[i][e] = 0.f;

    const int r0 = wm * 16 + g;
    const int r1 = r0 + 8;

    for (int kt = 0; kt < 16; ++kt) {
        const int k0 = kt << 6;
        __syncthreads();

        {
            const __nv_bfloat16* kh = g_sH[1] + ((size_t)bh * SEQ + k0) * 64;
            const __nv_bfloat16* kl = g_sL[1] + ((size_t)bh * SEQ + k0) * 64;
            #pragma unroll
            for (int it = 0; it < 2; ++it) {
                int idx = tid + it * 256;
                int r = idx >> 3, u = idx & 7;
                *(uint4*)(SM + OFF_KH + r * APB + u * 16) = *(const uint4*)(kh + r * 64 + u * 8);
                *(uint4*)(SM + OFF_KL + r * APB + u * 16) = *(const uint4*)(kl + r * 64 + u * 8);
            }
        }
        if (tid < 64) skm[tid] = kmask[b * SEQ + k0 + tid];
        __syncthreads();

        float sacc[4][4];
        #pragma unroll
        for (int i = 0; i < 4; ++i)
            #pragma unroll
            for (int e = 0; e < 4; ++e) sacc[i][e] = 0.f;
        #pragma unroll
        for (int kc = 0; kc < 4; ++kc) {
            uint32_t qh4[4], ql4[4];
            uint32_t aaddr = sb + OFF_QH + (wm * 16 + a_r) * APB + (kc * 16 + a_k) * 2;
            LDSM_X4(qh4, aaddr);
            LDSM_X4(ql4, aaddr + APLANE);
            #pragma unroll
            for (int tt = 0; tt < 2; ++tt) {
                uint32_t kh4[4], kl4[4];
                uint32_t baddr = sb + OFF_KH + (wn * 32 + tt * 16 + b_n) * APB + (kc * 16 + b_k) * 2;
                LDSM_X4(kh4, baddr);
                LDSM_X4(kl4, baddr + APLANE);
                #pragma unroll
                for (int hv = 0; hv < 2; ++hv) {
                    float* d = sacc[tt * 2 + hv];
                    MMA_BF16(d, qh4, kh4[2 * hv], kh4[2 * hv + 1]);
                    MMA_BF16(d, qh4, kl4[2 * hv], kl4[2 * hv + 1]);
                    MMA_BF16(d, ql4, kh4[2 * hv], kh4[2 * hv + 1]);
                }
            }
        }

        {
            size_t ar = (size_t)bh * SEQ + q0 + r0;
            #pragma unroll
            for (int nf = 0; nf < 4; ++nf) {
                size_t cb = (size_t)k0 + wn * 32 + nf * 8 + t * 2;
                *(float2*)(att + ar * SEQ + cb)       = make_float2(sacc[nf][0], sacc[nf][1]);
                *(float2*)(att + (ar + 8) * SEQ + cb) = make_float2(sacc[nf][2], sacc[nf][3]);
            }
        }

        const bool qv0 = (qmr[r0] != 0.f), qv1 = (qmr[r1] != 0.f);
        float sv[4][4];
        #pragma unroll
        for (int nf = 0; nf < 4; ++nf) {
            int col = wn * 32 + nf * 8 + t * 2;
            bool k0m = (skm[col] != 0.f), k1m = (skm[col + 1] != 0.f);
            sv[nf][0] = (qv0 && k0m) ? sacc[nf][0] * 0.125f : -1e9f;
            sv[nf][1] = (qv0 && k1m) ? sacc[nf][1] * 0.125f : -1e9f;
            sv[nf][2] = (qv1 && k0m) ? sacc[nf][2] * 0.125f : -1e9f;
            sv[nf][3] = (qv1 && k1m) ? sacc[nf][3] * 0.125f : -1e9f;
        }

        float m0 = -INFINITY, m1 = -INFINITY;
        #pragma unroll
        for (int nf = 0; nf < 4; ++nf) {
            m0 = fmaxf(m0, fmaxf(sv[nf][0], sv[nf][1]));
            m1 = fmaxf(m1, fmaxf(sv[nf][2], sv[nf][3]));
        }
        m0 = fmaxf(m0, __shfl_xor_sync(0xffffffffu, m0, 1));
        m0 = fmaxf(m0, __shfl_xor_sync(0xffffffffu, m0, 2));
        m1 = fmaxf(m1, __shfl_xor_sync(0xffffffffu, m1, 1));
        m1 = fmaxf(m1, __shfl_xor_sync(0xffffffffu, m1, 2));
        if (t == 0) { pm[r0 * 2 + wn] = m0; pm[r1 * 2 + wn] = m1; }
        __syncthreads();

        {
            const __nv_bfloat16* vh = g_sH[2] + ((size_t)bh * SEQ + k0) * 64;
            const __nv_bfloat16* vl = g_sL[2] + ((size_t)bh * SEQ + k0) * 64;
            #pragma unroll
            for (int it = 0; it < 2; ++it) {
                int idx = tid + it * 256;
                int r = idx >> 3, u = idx & 7;
                *(uint4*)(SM + OFF_KH + r * APB + u * 16) = *(const uint4*)(vh + r * 64 + u * 8);
                *(uint4*)(SM + OFF_KL + r * APB + u * 16) = *(const uint4*)(vl + r * 64 + u * 8);
            }
        }
        float mo0 = rowM[r0], mo1 = rowM[r1];
        float mn0 = fmaxf(mo0, fmaxf(pm[r0 * 2], pm[r0 * 2 + 1]));
        float mn1 = fmaxf(mo1, fmaxf(pm[r1 * 2], pm[r1 * 2 + 1]));
        float al0 = __expf(mo0 - mn0);
        float al1 = __expf(mo1 - mn1);
        __syncthreads();
        if (wn == 0 && t == 0) { rowM[r0] = mn0; rowM[r1] = mn1; }

        float pf[4][4];
        float ls0 = 0.f, ls1 = 0.f;
        #pragma unroll
        for (int nf = 0; nf < 4; ++nf) {
            pf[nf][0] = __expf(sv[nf][0] - mn0);
            pf[nf][1] = __expf(sv[nf][1] - mn0);
            pf[nf][2] = __expf(sv[nf][2] - mn1);
            pf[nf][3] = __expf(sv[nf][3] - mn1);
            ls0 += pf[nf][0] + pf[nf][1];
            ls1 += pf[nf][2] + pf[nf][3];
        }
        ls0 += __shfl_xor_sync(0xffffffffu, ls0, 1);
        ls0 += __shfl_xor_sync(0xffffffffu, ls0, 2);
        ls1 += __shfl_xor_sync(0xffffffffu, ls1, 1);
        ls1 += __shfl_xor_sync(0xffffffffu, ls1, 2);
        if (t == 0) { ps[r0 * 2 + wn] = ls0; ps[r1 * 2 + wn] = ls1; }
        __syncthreads();
        if (wn == 0 && t == 0) {
            rowL[r0] = rowL[r0] * al0 + ps[r0 * 2] + ps[r0 * 2 + 1];
            rowL[r1] = rowL[r1] * al1 + ps[r1 * 2] + ps[r1 * 2 + 1];
        }

        #pragma unroll
        for (int i = 0; i < 8; ++i) {
            cacc[i][0] *= al0; cacc[i][1] *= al0;
            cacc[i][2] *= al1; cacc[i][3] *= al1;
        }

        uint32_t pAh[2][4], pAl[2][4];
        #pragma unroll
        for (int kb = 0; kb < 2; ++kb) {
            float e00 = pf[2 * kb][0],     e01 = pf[2 * kb][1];
            float e10 = pf[2 * kb][2],     e11 = pf[2 * kb][3];
            float f00 = pf[2 * kb + 1][0], f01 = pf[2 * kb + 1][1];
            float f10 = pf[2 * kb + 1][2], f11 = pf[2 * kb + 1][3];
            uint32_t h0 = pack2(e00, e01), h1 = pack2(e10, e11);
            uint32_t h2 = pack2(f00, f01), h3 = pack2(f10, f11);
            pAh[kb][0] = h0; pAh[kb][1] = h1; pAh[kb][2] = h2; pAh[kb][3] = h3;
            pAl[kb][0] = pack2(e00 - lo_half_f(h0), e01 - hi_half_f(h0));
            pAl[kb][1] = pack2(e10 - lo_half_f(h1), e11 - hi_half_f(h1));
            pAl[kb][2] = pack2(f00 - lo_half_f(h2), f01 - hi_half_f(h2));
            pAl[kb][3] = pack2(f10 - lo_half_f(h3), f11 - hi_half_f(h3));
        }

        #pragma unroll
        for (int kb = 0; kb < 2; ++kb) {
            const int kbase = wn * 32 + kb * 16;
            #pragma unroll
            for (int dt = 0; dt < 4; ++dt) {
                uint32_t vh4[4], vl4[4];
                uint32_t vaddr = sb + OFF_KH + (kbase + v_r) * APB + (dt * 16 + v_c) * 2;
                LDSM_X4_T(vh4, vaddr);
                LDSM_X4_T(vl4, vaddr + APLANE);
                #pragma unroll
                for (int hv = 0; hv < 2; ++hv) {
                    float* d = cacc[dt * 2 + hv];
                    MMA_BF16(d, pAh[kb], vh4[2 * hv], vh4[2 * hv + 1]);
                    MMA_BF16(d, pAh[kb], vl4[2 * hv], vl4[2 * hv + 1]);
                    MMA_BF16(d, pAl[kb], vh4[2 * hv], vh4[2 * hv + 1]);
                }
            }
        }
    }

    __syncthreads();
    float* CB = (float*)SM;
    if (wn == 1) {
        #pragma unroll
        for (int i = 0; i < 8; ++i) {
            int c = i * 8 + t * 2;
            *(float2*)&CB[r0 * 66 + c] = make_float2(cacc[i][0], cacc[i][1]);
            *(float2*)&CB[r1 * 66 + c] = make_float2(cacc[i][2], cacc[i][3]);
        }
    }
    __syncthreads();
    if (wn == 0) {
        float inv0 = (qmr[r0] != 0.f) ? 1.f / rowL[r0] : 0.f;
        float inv1 = (qmr[r1] != 0.f) ? 1.f / rowL[r1] : 0.f;
        size_t m0r = (size_t)(b * SEQ + q0 + r0) * DIN + h * 64;
        size_t m1r = (size_t)(b * SEQ + q0 + r1) * DIN + h * 64;
        #pragma unroll
        for (int i = 0; i < 8; ++i) {
            int c = i * 8 + t * 2;
            float x0 = (cacc[i][0] + CB[r0 * 66 + c])     * inv0;
            float x1 = (cacc[i][1] + CB[r0 * 66 + c + 1]) * inv0;
            float y0 = (cacc[i][2] + CB[r1 * 66 + c])     * inv1;
            float y1 = (cacc[i][3] + CB[r1 * 66 + c + 1]) * inv1;
            uint32_t hx = pack2(x0, x1);
            uint32_t hy = pack2(y0, y1);
            *(uint32_t*)(g_Xh + m0r + c) = hx;
            *(uint32_t*)(g_Xl + m0r + c) = pack2(x0 - lo_half_f(hx), x1 - hi_half_f(hx));
            *(uint32_t*)(g_Xh + m1r + c) = hy;
            *(uint32_t*)(g_Xl + m1r + c) = pack2(y0 - lo_half_f(hy), y1 - hi_half_f(hy));
        }
    }
}

// =====================================================================
// LayerNorm over last dim (1024), one block per row.
// =====================================================================
__global__ __launch_bounds__(256) void ln_kernel(
    const float* __restrict__ gamma, const float* __restrict__ beta,
    float* __restrict__ out)
{
    __shared__ float red[16];
    __shared__ float s_mu, s_rs;
    const int row = blockIdx.x;
    const int tid = threadIdx.x;
    const float* xr = g_O1 + (size_t)row * DIN;
    float4 x = *(const float4*)(xr + tid * 4);
    float s  = x.x + x.y + x.z + x.w;
    float s2 = x.x * x.x + x.y * x.y + x.z * x.z + x.w * x.w;
    #pragma unroll
    for (int o = 16; o; o >>= 1) {
        s  += __shfl_xor_sync(0xffffffffu, s, o);
        s2 += __shfl_xor_sync(0xffffffffu, s2, o);
    }
    if ((tid & 31) == 0) { red[tid >> 5] = s; red[8 + (tid >> 5)] = s2; }
    __syncthreads();
    if (tid == 0) {
        float ts = 0.f, ts2 = 0.f;
        #pragma unroll
        for (int w = 0; w < 8; w++) { ts += red[w]; ts2 += red[8 + w]; }
        float mu  = ts * (1.f / 1024.f);
        float var = ts2 * (1.f / 1024.f) - mu * mu;
        s_mu = mu; s_rs = rsqrtf(var + 1e-5f);
    }
    __syncthreads();
    float mu = s_mu, rs = s_rs;
    float4 g  = *(const float4*)(gamma + tid * 4);
    float4 be = *(const float4*)(beta  + tid * 4);
    float4 o;
    o.x = (x.x - mu) * rs * g.x + be.x;
    o.y = (x.y - mu) * rs * g.y + be.y;
    o.z = (x.z - mu) * rs * g.z + be.z;
    o.w = (x.w - mu) * rs * g.w + be.w;
    *(float4*)(out + (size_t)row * DIN + tid * 4) = o;
}

// =====================================================================
extern "C" void kernel_launch(void* const* d_in, const int* in_sizes, int n_in,
                              void* d_out, int out_size)
{
    const float* q     = (const float*)d_in[0];
    const float* k     = (const float*)d_in[1];
    const float* v     = (const float*)d_in[2];
    const float* qm    = (const float*)d_in[3];
    const float* km    = (const float*)d_in[4];
    const float* Wq    = (const float*)d_in[5];
    const float* bq    = (const float*)d_in[6];
    const float* Wk    = (const float*)d_in[7];
    const float* bk    = (const float*)d_in[8];
    const float* Wv    = (const float*)d_in[9];
    const float* bv    = (const float*)d_in[10];
    const float* Wf    = (const float*)d_in[11];
    const float* bf    = (const float*)d_in[12];
    const float* gamma = (const float*)d_in[13];
    const float* beta  = (const float*)d_in[14];

    float* out = (float*)d_out;
    float* att = out + OUT1_ELEMS;

    cudaFuncSetAttribute(gemm_mma, cudaFuncAttributeMaxDynamicSharedMemorySize, GEMM_SMEM);

    const int cvx_blocks = (int)(OUT1_ELEMS / (4 * 256));   // 4096
    const dim3 cw(32, 32);
    const dim3 gg(DIN / 128, MTOT / 128);                   // (8, 32)

    cvt_x<<<cvx_blocks, 256>>>(q);
    cvt_w<<<cw, 256>>>(Wq);
    gemm_mma<<<gg, 256, GEMM_SMEM>>>(bq, nullptr, 0);

    cvt_x<<<cvx_blocks, 256>>>(k);
    cvt_w<<<cw, 256>>>(Wk);
    gemm_mma<<<gg, 256, GEMM_SMEM>>>(bk, nullptr, 1);

    cvt_x<<<cvx_blocks, 256>>>(v);
    cvt_w<<<cw, 256>>>(Wv);
    gemm_mma<<<gg, 256, GEMM_SMEM>>>(bv, nullptr, 2);

    attn_mma<<<dim3(SEQ / 64, NB * NH), 256>>>(qm, km, att);

    cvt_w<<<cw, 256>>>(Wf);
    gemm_mma<<<gg, 256, GEMM_SMEM>>>(bf, v, 3);   // reads g_Xh/g_Xl from attn finalize

    ln_kernel<<<MTOT, 256>>>(gamma, beta, out);
}

// round 17
// speedup vs baseline: 2.0037x; 2.0037x over previous
#include <cuda_runtime.h>
#include <cuda_fp16.h>
#include <math.h>
#include <stdint.h>

// ---------------- problem constants ----------------
constexpr int NB   = 4;
constexpr int SEQ  = 1024;
constexpr int DIN  = 1024;
constexpr int NH   = 16;
constexpr int MTOT = NB * SEQ;                       // 4096
constexpr size_t OUT1_ELEMS = (size_t)MTOT * DIN;    // 4,194,304
// d_out layout: [ out (4M floats) | attention (64M floats) ]

// ---------------- scratch (device globals; no allocation) ----------------
__device__ float g_O1 [OUT1_ELEMS];                  // final proj + bias + resid
// fp16 GEMM operands: X planes [m][k] (0=q,1=k,2=v,3=ctx), W planes [n][k]
__device__ __half g_X[4][OUT1_ELEMS];
__device__ __half g_W[4][(size_t)DIN * DIN];
// projected Q/K/V in fp16 head layout [(b*NH+h)*SEQ + s][64]
__device__ __half g_s[3][OUT1_ELEMS];

// =====================================================================
// helpers (plain-sm_103-safe: ldmatrix + mma.sync only)
// =====================================================================
__device__ __forceinline__ uint32_t smem_u32(const void* p) {
    return (uint32_t)__cvta_generic_to_shared(p);
}

#define LDSM_X4(r, addr)                                                        \
    asm volatile("ldmatrix.sync.aligned.m8n8.x4.shared.b16 {%0,%1,%2,%3}, [%4];"\
        : "=r"((r)[0]), "=r"((r)[1]), "=r"((r)[2]), "=r"((r)[3]) : "r"(addr))

#define LDSM_X4_T(r, addr)                                                      \
    asm volatile("ldmatrix.sync.aligned.m8n8.x4.trans.shared.b16 {%0,%1,%2,%3}, [%4];"\
        : "=r"((r)[0]), "=r"((r)[1]), "=r"((r)[2]), "=r"((r)[3]) : "r"(addr))

#define MMA_F16(d, a, b0, b1)                                                   \
    asm volatile("mma.sync.aligned.m16n8k16.row.col.f32.f16.f16.f32 "           \
        "{%0,%1,%2,%3}, {%4,%5,%6,%7}, {%8,%9}, {%0,%1,%2,%3};"                 \
        : "+f"((d)[0]), "+f"((d)[1]), "+f"((d)[2]), "+f"((d)[3])                \
        : "r"((a)[0]), "r"((a)[1]), "r"((a)[2]), "r"((a)[3]), "r"(b0), "r"(b1))

// pack two floats to fp16x2 (RN): e0 -> low 16 bits, e1 -> high 16 bits
__device__ __forceinline__ uint32_t pack2(float e0, float e1) {
    __half2 h = __floats2half2_rn(e0, e1);
    return *(uint32_t*)&h;
}

// =====================================================================
// cvt_x3: fp32 -> fp16 plane, inputs q/k/v chosen by blockIdx.y.
// =====================================================================
__global__ __launch_bounds__(256) void cvt_x3(
    const float* __restrict__ q, const float* __restrict__ k,
    const float* __restrict__ v)
{
    const float* src = (blockIdx.y == 0) ? q : (blockIdx.y == 1) ? k : v;
    size_t i = ((size_t)blockIdx.x * 256 + threadIdx.x) * 4;
    float4 x = *(const float4*)(src + i);
    *(uint2*)(g_X[blockIdx.y] + i) = make_uint2(pack2(x.x, x.y), pack2(x.z, x.w));
}

// =====================================================================
// cvt_w4: W[k][n] fp32 -> transposed fp16 g_W[z][n][k]; z = blockIdx.z.
// 32x32 tiles via smem.
// =====================================================================
__global__ __launch_bounds__(256) void cvt_w4(
    const float* __restrict__ Wq, const float* __restrict__ Wk,
    const float* __restrict__ Wv, const float* __restrict__ Wf)
{
    const int z = blockIdx.z;
    const float* W = (z == 0) ? Wq : (z == 1) ? Wk : (z == 2) ? Wv : Wf;
    __shared__ float t[32][33];
    const int k0 = blockIdx.y * 32, n0 = blockIdx.x * 32;
    const int tx = threadIdx.x & 31, ty = threadIdx.x >> 5;
    #pragma unroll
    for (int p = 0; p < 4; ++p) {
        int r = ty + p * 8;
        t[r][tx] = W[(size_t)(k0 + r) * DIN + n0 + tx];
    }
    __syncthreads();
    const int nl = threadIdx.x >> 4;              // 0..15 n-local
    const int pr = threadIdx.x & 15;              // k-pair
    #pragma unroll
    for (int p = 0; p < 2; ++p) {
        int n = nl + p * 16;
        size_t off = (size_t)(n0 + n) * DIN + k0 + 2 * pr;
        *(uint32_t*)(g_W[z] + off) = pack2(t[2 * pr][n], t[2 * pr + 1][n]);
    }
}

// =====================================================================
// fp16 HMMA GEMM: C[m,n] = sum_k X[m,k] W[k,n], SINGLE mma per k16 step.
// CTA tile 128x128, K-chunk 64, 256 threads = 8 warps (4M x 2N).
// plane p = base + blockIdx.z. p<3: epilogue -> fp16 head layout g_s[p].
// p==3: epilogue -> g_O1 fp32 (+bias +resid).
// Fragment address math identical to R12/R13-validated bf16 kernel.
// =====================================================================
constexpr int SPITCH = 144;                // 128B row + 16B pad (conflict-free ldsm)
constexpr int PLANE  = 128 * SPITCH;       // 18432 B
// static smem: 2 planes (A, B) = 36864 B

__global__ __launch_bounds__(256) void gemm_f16(
    const float* __restrict__ b0, const float* __restrict__ b1,
    const float* __restrict__ b2, const float* __restrict__ resid, int base)
{
    __shared__ __align__(16) unsigned char smem[2 * PLANE];
    const uint32_t sb = smem_u32(smem);

    const int tid = threadIdx.x;
    const int w   = tid >> 5, ln = tid & 31;
    const int wm  = w & 3, wn = w >> 2;
    const int m0  = blockIdx.y * 128;
    const int n0  = blockIdx.x * 128;
    const int p   = base + blockIdx.z;
    const int z   = blockIdx.z;
    const float* bias = (z == 0) ? b0 : (z == 1) ? b1 : b2;

    const __half* Asrc = g_X[p] + (size_t)m0 * DIN;
    const __half* Bsrc = g_W[p] + (size_t)n0 * DIN;

    const int a_r = (ln & 7) + ((ln >> 3) & 1) * 8;
    const int a_k = ((ln >> 4) & 1) * 8;
    const int b_n = (ln & 7) + ((ln >> 4) & 1) * 8;
    const int b_k = ((ln >> 3) & 1) * 8;

    float acc[2][8][4];
    #pragma unroll
    for (int i = 0; i < 2; ++i)
        #pragma unroll
        for (int j = 0; j < 8; ++j)
            #pragma unroll
            for (int e = 0; e < 4; ++e) acc[i][j][e] = 0.f;

    for (int ch = 0; ch < 16; ++ch) {
        const int k0 = ch * 64;
        // ---- stage A and B planes: 128 rows x 128B each ----
        #pragma unroll
        for (int pl = 0; pl < 2; ++pl) {
            const __half* s = (pl ? Bsrc : Asrc) + k0;
            #pragma unroll
            for (int it = 0; it < 4; ++it) {
                int idx = tid + it * 256;          // 0..1023 16B-units
                int r = idx >> 3, u = idx & 7;
                uint4 vv = *(const uint4*)(s + (size_t)r * DIN + u * 8);
                *(uint4*)(smem + pl * PLANE + r * SPITCH + u * 16) = vv;
            }
        }
        __syncthreads();

        #pragma unroll
        for (int kk = 0; kk < 64; kk += 16) {
            uint32_t af[2][4];
            #pragma unroll
            for (int mf = 0; mf < 2; ++mf)
                LDSM_X4(af[mf], sb + (wm * 32 + mf * 16 + a_r) * SPITCH + (kk + a_k) * 2);
            #pragma unroll
            for (int t = 0; t < 4; ++t) {
                uint32_t bf4[4];
                LDSM_X4(bf4, sb + PLANE + (wn * 64 + t * 16 + b_n) * SPITCH + (kk + b_k) * 2);
                #pragma unroll
                for (int mf = 0; mf < 2; ++mf)
                    #pragma unroll
                    for (int hv = 0; hv < 2; ++hv)
                        MMA_F16(acc[mf][t * 2 + hv], af[mf], bf4[2 * hv], bf4[2 * hv + 1]);
            }
        }
        __syncthreads();
    }

    const int rbase = m0 + wm * 32 + (ln >> 2);
    const int cbase = n0 + wn * 64 + (ln & 3) * 2;
    if (p < 3) {
        __half* oh = g_s[p];
        #pragma unroll
        for (int mf = 0; mf < 2; ++mf)
            #pragma unroll
            for (int nf = 0; nf < 8; ++nf) {
                int c = cbase + nf * 8;
                int h = c >> 6, d = c & 63;
                float bx = bias[c], by = bias[c + 1];
                #pragma unroll
                for (int half = 0; half < 2; ++half) {
                    int m = rbase + mf * 16 + half * 8;
                    int b = m >> 10, s = m & 1023;
                    size_t off = ((size_t)((b * NH + h) * SEQ + s)) * 64 + d;
                    *(uint32_t*)(oh + off) =
                        pack2(acc[mf][nf][2 * half + 0] + bx,
                              acc[mf][nf][2 * half + 1] + by);
                }
            }
    } else {
        #pragma unroll
        for (int mf = 0; mf < 2; ++mf)
            #pragma unroll
            for (int nf = 0; nf < 8; ++nf) {
                int c = cbase + nf * 8;
                float bx = bias[c], by = bias[c + 1];
                #pragma unroll
                for (int half = 0; half < 2; ++half) {
                    int r = rbase + mf * 16 + half * 8;
                    float2 rv = *(const float2*)(resid + (size_t)r * DIN + c);
                    *(float2*)(g_O1 + (size_t)r * DIN + c) =
                        make_float2(acc[mf][nf][2 * half + 0] + bx + rv.x,
                                    acc[mf][nf][2 * half + 1] + by + rv.y);
                }
            }
    }
}

// =====================================================================
// Tensor-core flash attention (R13-validated structure, fp16 single-plane).
// Block: (b,h) x 64-row q-tile. 8 warps: wm = q-band(16), wn = kseq half(32).
// =====================================================================
constexpr int APB = 144;                      // 64 fp16 = 128B row + 16B pad
constexpr int APLANE = 64 * APB;              // 9216
constexpr int OFF_QH = 0;
constexpr int OFF_KH = OFF_QH + APLANE;       // reused for V
constexpr int OFF_PM = OFF_KH + APLANE;       // 18432: pm[64][2] f32
constexpr int OFF_PS = OFF_PM + 512;
constexpr int OFF_RM = OFF_PS + 512;
constexpr int OFF_RL = OFF_RM + 256;
constexpr int OFF_QM = OFF_RL + 256;
constexpr int OFF_KM = OFF_QM + 256;
constexpr int ATT_SM = OFF_KM + 256;          // 20224 B (static)
// finalize combine buffer [64][66] f32 = 16896 B aliases QH/KH region

__global__ __launch_bounds__(256) void attn_mma(
    const float* __restrict__ qmask, const float* __restrict__ kmask,
    float* __restrict__ att)
{
    __shared__ __align__(16) unsigned char SM[ATT_SM];
    const uint32_t sb = smem_u32(SM);
    float* pm   = (float*)(SM + OFF_PM);
    float* ps   = (float*)(SM + OFF_PS);
    float* rowM = (float*)(SM + OFF_RM);
    float* rowL = (float*)(SM + OFF_RL);
    float* qmr  = (float*)(SM + OFF_QM);
    float* skm  = (float*)(SM + OFF_KM);

    const int tid = threadIdx.x;
    const int w   = tid >> 5, ln = tid & 31;
    const int wm  = w & 3, wn = w >> 2;
    const int g   = ln >> 2, t = ln & 3;
    const int bh  = blockIdx.y;
    const int b   = bh >> 4, h = bh & 15;
    const int q0  = blockIdx.x << 6;

    const int a_r = (ln & 7) + ((ln >> 3) & 1) * 8;
    const int a_k = ((ln >> 4) & 1) * 8;
    const int b_n = (ln & 7) + ((ln >> 4) & 1) * 8;
    const int b_k = ((ln >> 3) & 1) * 8;
    const int v_r = (ln & 7) + ((ln >> 3) & 1) * 8;
    const int v_c = ((ln >> 4) & 1) * 8;

    {   // Q tile: 64 rows x 8 16B-units
        const __half* qh = g_s[0] + ((size_t)bh * SEQ + q0) * 64;
        #pragma unroll
        for (int it = 0; it < 2; ++it) {
            int idx = tid + it * 256;             // 0..511
            int r = idx >> 3, u = idx & 7;
            *(uint4*)(SM + OFF_QH + r * APB + u * 16) = *(const uint4*)(qh + r * 64 + u * 8);
        }
    }
    if (tid < 64) {
        qmr[tid]  = qmask[b * SEQ + q0 + tid];
        rowM[tid] = -INFINITY;
        rowL[tid] = 0.f;
    }

    float cacc[8][4];
    #pragma unroll
    for (int i = 0; i < 8; ++i)
        #pragma unroll
        for (int e = 0; e < 4; ++e) cacc[i][e] = 0.f;

    const int r0 = wm * 16 + g;
    const int r1 = r0 + 8;

    for (int kt = 0; kt < 16; ++kt) {
        const int k0 = kt << 6;
        __syncthreads();   // prev V reads done; KV buffer reusable

        {   // K tile
            const __half* kh = g_s[1] + ((size_t)bh * SEQ + k0) * 64;
            #pragma unroll
            for (int it = 0; it < 2; ++it) {
                int idx = tid + it * 256;
                int r = idx >> 3, u = idx & 7;
                *(uint4*)(SM + OFF_KH + r * APB + u * 16) = *(const uint4*)(kh + r * 64 + u * 8);
            }
        }
        if (tid < 64) skm[tid] = kmask[b * SEQ + k0 + tid];
        __syncthreads();

        // ---- S = Q K^T ----
        float sacc[4][4];
        #pragma unroll
        for (int i = 0; i < 4; ++i)
            #pragma unroll
            for (int e = 0; e < 4; ++e) sacc[i][e] = 0.f;
        #pragma unroll
        for (int kc = 0; kc < 4; ++kc) {
            uint32_t qf[4];
            LDSM_X4(qf, sb + OFF_QH + (wm * 16 + a_r) * APB + (kc * 16 + a_k) * 2);
            #pragma unroll
            for (int tt = 0; tt < 2; ++tt) {
                uint32_t kf[4];
                LDSM_X4(kf, sb + OFF_KH + (wn * 32 + tt * 16 + b_n) * APB + (kc * 16 + b_k) * 2);
                #pragma unroll
                for (int hv = 0; hv < 2; ++hv)
                    MMA_F16(sacc[tt * 2 + hv], qf, kf[2 * hv], kf[2 * hv + 1]);
            }
        }

        {   // raw logits -> gmem (output #2)
            size_t ar = (size_t)bh * SEQ + q0 + r0;
            #pragma unroll
            for (int nf = 0; nf < 4; ++nf) {
                size_t cb = (size_t)k0 + wn * 32 + nf * 8 + t * 2;
                *(float2*)(att + ar * SEQ + cb)       = make_float2(sacc[nf][0], sacc[nf][1]);
                *(float2*)(att + (ar + 8) * SEQ + cb) = make_float2(sacc[nf][2], sacc[nf][3]);
            }
        }

        const bool qv0 = (qmr[r0] != 0.f), qv1 = (qmr[r1] != 0.f);
        float sv[4][4];
        #pragma unroll
        for (int nf = 0; nf < 4; ++nf) {
            int col = wn * 32 + nf * 8 + t * 2;
            bool k0m = (skm[col] != 0.f), k1m = (skm[col + 1] != 0.f);
            sv[nf][0] = (qv0 && k0m) ? sacc[nf][0] * 0.125f : -1e9f;
            sv[nf][1] = (qv0 && k1m) ? sacc[nf][1] * 0.125f : -1e9f;
            sv[nf][2] = (qv1 && k0m) ? sacc[nf][2] * 0.125f : -1e9f;
            sv[nf][3] = (qv1 && k1m) ? sacc[nf][3] * 0.125f : -1e9f;
        }

        float m0 = -INFINITY, m1 = -INFINITY;
        #pragma unroll
        for (int nf = 0; nf < 4; ++nf) {
            m0 = fmaxf(m0, fmaxf(sv[nf][0], sv[nf][1]));
            m1 = fmaxf(m1, fmaxf(sv[nf][2], sv[nf][3]));
        }
        m0 = fmaxf(m0, __shfl_xor_sync(0xffffffffu, m0, 1));
        m0 = fmaxf(m0, __shfl_xor_sync(0xffffffffu, m0, 2));
        m1 = fmaxf(m1, __shfl_xor_sync(0xffffffffu, m1, 1));
        m1 = fmaxf(m1, __shfl_xor_sync(0xffffffffu, m1, 2));
        if (t == 0) { pm[r0 * 2 + wn] = m0; pm[r1 * 2 + wn] = m1; }
        __syncthreads();          // partials visible; K ldmatrix reads done

        {   // V tile (reuses K buffer)
            const __half* vh = g_s[2] + ((size_t)bh * SEQ + k0) * 64;
            #pragma unroll
            for (int it = 0; it < 2; ++it) {
                int idx = tid + it * 256;
                int r = idx >> 3, u = idx & 7;
                *(uint4*)(SM + OFF_KH + r * APB + u * 16) = *(const uint4*)(vh + r * 64 + u * 8);
            }
        }
        float mo0 = rowM[r0], mo1 = rowM[r1];
        float mn0 = fmaxf(mo0, fmaxf(pm[r0 * 2], pm[r0 * 2 + 1]));
        float mn1 = fmaxf(mo1, fmaxf(pm[r1 * 2], pm[r1 * 2 + 1]));
        float al0 = __expf(mo0 - mn0);
        float al1 = __expf(mo1 - mn1);
        __syncthreads();          // V staged; everyone read old rowM/pm
        if (wn == 0 && t == 0) { rowM[r0] = mn0; rowM[r1] = mn1; }

        float pf[4][4];
        float ls0 = 0.f, ls1 = 0.f;
        #pragma unroll
        for (int nf = 0; nf < 4; ++nf) {
            pf[nf][0] = __expf(sv[nf][0] - mn0);
            pf[nf][1] = __expf(sv[nf][1] - mn0);
            pf[nf][2] = __expf(sv[nf][2] - mn1);
            pf[nf][3] = __expf(sv[nf][3] - mn1);
            ls0 += pf[nf][0] + pf[nf][1];
            ls1 += pf[nf][2] + pf[nf][3];
        }
        ls0 += __shfl_xor_sync(0xffffffffu, ls0, 1);
        ls0 += __shfl_xor_sync(0xffffffffu, ls0, 2);
        ls1 += __shfl_xor_sync(0xffffffffu, ls1, 1);
        ls1 += __shfl_xor_sync(0xffffffffu, ls1, 2);
        if (t == 0) { ps[r0 * 2 + wn] = ls0; ps[r1 * 2 + wn] = ls1; }
        __syncthreads();
        if (wn == 0 && t == 0) {
            rowL[r0] = rowL[r0] * al0 + ps[r0 * 2] + ps[r0 * 2 + 1];
            rowL[r1] = rowL[r1] * al1 + ps[r1 * 2] + ps[r1 * 2 + 1];
        }

        #pragma unroll
        for (int i = 0; i < 8; ++i) {
            cacc[i][0] *= al0; cacc[i][1] *= al0;
            cacc[i][2] *= al1; cacc[i][3] *= al1;
        }

        // ---- P fragments (S-accum layout == A-frag layout), fp16 ----
        uint32_t pA[2][4];
        #pragma unroll
        for (int kb = 0; kb < 2; ++kb) {
            pA[kb][0] = pack2(pf[2 * kb][0],     pf[2 * kb][1]);
            pA[kb][1] = pack2(pf[2 * kb][2],     pf[2 * kb][3]);
            pA[kb][2] = pack2(pf[2 * kb + 1][0], pf[2 * kb + 1][1]);
            pA[kb][3] = pack2(pf[2 * kb + 1][2], pf[2 * kb + 1][3]);
        }

        // ---- ctx += P V (V^T via ldmatrix.trans) ----
        #pragma unroll
        for (int kb = 0; kb < 2; ++kb) {
            const int kbase = wn * 32 + kb * 16;
            #pragma unroll
            for (int dt = 0; dt < 4; ++dt) {
                uint32_t vf[4];
                LDSM_X4_T(vf, sb + OFF_KH + (kbase + v_r) * APB + (dt * 16 + v_c) * 2);
                #pragma unroll
                for (int hv = 0; hv < 2; ++hv)
                    MMA_F16(cacc[dt * 2 + hv], pA[kb], vf[2 * hv], vf[2 * hv + 1]);
            }
        }
    }

    // ---- finalize: combine wn halves, divide, mask, write fp16 X-plane 3 ----
    __syncthreads();
    float* CB = (float*)SM;                   // [64][66] f32, aliases Q/K planes
    if (wn == 1) {
        #pragma unroll
        for (int i = 0; i < 8; ++i) {
            int c = i * 8 + t * 2;
            *(float2*)&CB[r0 * 66 + c] = make_float2(cacc[i][0], cacc[i][1]);
            *(float2*)&CB[r1 * 66 + c] = make_float2(cacc[i][2], cacc[i][3]);
        }
    }
    __syncthreads();
    if (wn == 0) {
        float inv0 = (qmr[r0] != 0.f) ? 1.f / rowL[r0] : 0.f;
        float inv1 = (qmr[r1] != 0.f) ? 1.f / rowL[r1] : 0.f;
        size_t m0r = (size_t)(b * SEQ + q0 + r0) * DIN + h * 64;
        size_t m1r = (size_t)(b * SEQ + q0 + r1) * DIN + h * 64;
        #pragma unroll
        for (int i = 0; i < 8; ++i) {
            int c = i * 8 + t * 2;
            *(uint32_t*)(g_X[3] + m0r + c) =
                pack2((cacc[i][0] + CB[r0 * 66 + c])     * inv0,
                      (cacc[i][1] + CB[r0 * 66 + c + 1]) * inv0);
            *(uint32_t*)(g_X[3] + m1r + c) =
                pack2((cacc[i][2] + CB[r1 * 66 + c])     * inv1,
                      (cacc[i][3] + CB[r1 * 66 + c + 1]) * inv1);
        }
    }
}

// =====================================================================
// LayerNorm over last dim (1024), one block per row.
// =====================================================================
__global__ __launch_bounds__(256) void ln_kernel(
    const float* __restrict__ gamma, const float* __restrict__ beta,
    float* __restrict__ out)
{
    __shared__ float red[16];
    __shared__ float s_mu, s_rs;
    const int row = blockIdx.x;
    const int tid = threadIdx.x;
    const float* xr = g_O1 + (size_t)row * DIN;
    float4 x = *(const float4*)(xr + tid * 4);
    float s  = x.x + x.y + x.z + x.w;
    float s2 = x.x * x.x + x.y * x.y + x.z * x.z + x.w * x.w;
    #pragma unroll
    for (int o = 16; o; o >>= 1) {
        s  += __shfl_xor_sync(0xffffffffu, s, o);
        s2 += __shfl_xor_sync(0xffffffffu, s2, o);
    }
    if ((tid & 31) == 0) { red[tid >> 5] = s; red[8 + (tid >> 5)] = s2; }
    __syncthreads();
    if (tid == 0) {
        float ts = 0.f, ts2 = 0.f;
        #pragma unroll
        for (int w = 0; w < 8; w++) { ts += red[w]; ts2 += red[8 + w]; }
        float mu  = ts * (1.f / 1024.f);
        float var = ts2 * (1.f / 1024.f) - mu * mu;
        s_mu = mu; s_rs = rsqrtf(var + 1e-5f);
    }
    __syncthreads();
    float mu = s_mu, rs = s_rs;
    float4 g  = *(const float4*)(gamma + tid * 4);
    float4 be = *(const float4*)(beta  + tid * 4);
    float4 o;
    o.x = (x.x - mu) * rs * g.x + be.x;
    o.y = (x.y - mu) * rs * g.y + be.y;
    o.z = (x.z - mu) * rs * g.z + be.z;
    o.w = (x.w - mu) * rs * g.w + be.w;
    *(float4*)(out + (size_t)row * DIN + tid * 4) = o;
}

// =====================================================================
extern "C" void kernel_launch(void* const* d_in, const int* in_sizes, int n_in,
                              void* d_out, int out_size)
{
    const float* q     = (const float*)d_in[0];
    const float* k     = (const float*)d_in[1];
    const float* v     = (const float*)d_in[2];
    const float* qm    = (const float*)d_in[3];
    const float* km    = (const float*)d_in[4];
    const float* Wq    = (const float*)d_in[5];
    const float* bq    = (const float*)d_in[6];
    const float* Wk    = (const float*)d_in[7];
    const float* bk    = (const float*)d_in[8];
    const float* Wv    = (const float*)d_in[9];
    const float* bv    = (const float*)d_in[10];
    const float* Wf    = (const float*)d_in[11];
    const float* bf    = (const float*)d_in[12];
    const float* gamma = (const float*)d_in[13];
    const float* beta  = (const float*)d_in[14];

    float* out = (float*)d_out;
    float* att = out + OUT1_ELEMS;

    // all weight + input conversions up front (independent)
    cvt_w4<<<dim3(32, 32, 4), 256>>>(Wq, Wk, Wv, Wf);
    cvt_x3<<<dim3(4096, 3), 256>>>(q, k, v);

    // fused QKV projections: grid.z selects plane/weight/bias/output
    gemm_f16<<<dim3(8, 32, 3), 256>>>(bq, bk, bv, nullptr, 0);

    attn_mma<<<dim3(SEQ / 64, NB * NH), 256>>>(qm, km, att);

    // final projection (reads g_X[3] written by attn finalize)
    gemm_f16<<<dim3(8, 32, 1), 256>>>(bf, bf, bf, v, 3);

    ln_kernel<<<MTOT, 256>>>(gamma, beta, out);
}